// round 1
// baseline (speedup 1.0000x reference)
#include <cuda_runtime.h>
#include <cstdint>
#include <cstddef>

namespace {
constexpr int Bc = 4, Nc = 16384, Kc = 32, Dc = 64;
constexpr int WPB = 4;                 // warps per block
constexpr int NTHREADS = WPB * 32;
constexpr int HSS = Dc + 4;            // padded hs row stride (floats)
constexpr int POINTS = Bc * Nc;
constexpr int NBLOCKS = 1024;

union F2U { float2 f; unsigned long long u; };

__device__ __forceinline__ unsigned long long ffma2(unsigned long long a,
                                                    unsigned long long b,
                                                    unsigned long long c) {
    unsigned long long d;
    asm("fma.rn.f32x2 %0, %1, %2, %3;" : "=l"(d) : "l"(a), "l"(b), "l"(c));
    return d;
}
__device__ __forceinline__ unsigned long long fadd2(unsigned long long a,
                                                    unsigned long long b) {
    unsigned long long d;
    asm("add.rn.f32x2 %0, %1, %2;" : "=l"(d) : "l"(a), "l"(b));
    return d;
}
__device__ __forceinline__ unsigned long long pack2(float lo, float hi) {
    F2U t; t.f = make_float2(lo, hi); return t.u;
}
} // namespace

__global__ void __launch_bounds__(NTHREADS, 2) pointconv_kernel(
    const float* __restrict__ x,      // [B, N, 64]
    const float* __restrict__ pos,    // [B, N, 3]
    const int*   __restrict__ nidx,   // [B, N, 32]
    const float* __restrict__ W1,     // [3, 64]
    const float* __restrict__ b1,     // [64]
    const float* __restrict__ W2,     // [64, 64]
    const float* __restrict__ b2,     // [64]
    float*       __restrict__ out)    // [B, N, 64]
{
    __shared__ __align__(16) float w1s[3][Dc];
    __shared__ __align__(16) float b1s[Dc];
    __shared__ __align__(16) float hs[WPB][Kc][HSS];
    __shared__ int idxs[WPB][Kc];

    const int tid  = threadIdx.x;
    const int warp = tid >> 5;
    const int lane = tid & 31;
    const int f0   = 2 * lane;        // this lane owns features f0, f0+1

    if (tid < Dc) {
        w1s[0][tid] = W1[tid];
        w1s[1][tid] = W1[Dc + tid];
        w1s[2][tid] = W1[2 * Dc + tid];
        b1s[tid]    = b1[tid];
    }
    __syncthreads();

    // W2 columns for f0 / f0+1, packed as f32x2 pairs over consecutive g rows:
    //   w2q0[m] = (W2[2m][f0],   W2[2m+1][f0])
    //   w2q1[m] = (W2[2m][f0+1], W2[2m+1][f0+1])
    // This pairs directly with (h[2m], h[2m+1]) read as a packed 64-bit word
    // from shared — no pack instructions in the hot loop.
    unsigned long long w2q0[32], w2q1[32];
#pragma unroll
    for (int m = 0; m < 32; ++m) {
        const float a0 = W2[(2 * m)     * Dc + f0];
        const float a1 = W2[(2 * m + 1) * Dc + f0];
        const float c0 = W2[(2 * m)     * Dc + f0 + 1];
        const float c1 = W2[(2 * m + 1) * Dc + f0 + 1];
        w2q0[m] = pack2(a0, a1);
        w2q1[m] = pack2(c0, c1);
    }
    const unsigned long long b2i0 = pack2(b2[f0],     0.0f);
    const unsigned long long b2i1 = pack2(b2[f0 + 1], 0.0f);

    for (int p = blockIdx.x * WPB + warp; p < POINTS; p += NBLOCKS * WPB) {
        const int b = p >> 14;                    // p / N
        const float* xb = x + ((size_t)b * Nc) * Dc;

        // ---- phase 0: lane k loads its neighbor index ----
        const int j = nidx[(size_t)p * Kc + lane];
        idxs[warp][lane] = j;

        // ---- phase 1: lane k computes h_k[0..63] into shared ----
        const float* cp  = pos + (size_t)p * 3;
        const float cx = cp[0], cy = cp[1], cz = cp[2];
        const float* np_ = pos + ((size_t)b * Nc + j) * 3;
        const float rx = cx - np_[0], ry = cy - np_[1], rz = cz - np_[2];

#pragma unroll
        for (int g4 = 0; g4 < 16; ++g4) {
            const float4 a0 = *(const float4*)&w1s[0][g4 * 4];
            const float4 a1 = *(const float4*)&w1s[1][g4 * 4];
            const float4 a2 = *(const float4*)&w1s[2][g4 * 4];
            const float4 bb = *(const float4*)&b1s[g4 * 4];
            float4 z;
            z.x = fmaf(rx, a0.x, fmaf(ry, a1.x, fmaf(rz, a2.x, bb.x)));
            z.y = fmaf(rx, a0.y, fmaf(ry, a1.y, fmaf(rz, a2.y, bb.y)));
            z.z = fmaf(rx, a0.z, fmaf(ry, a1.z, fmaf(rz, a2.z, bb.z)));
            z.w = fmaf(rx, a0.w, fmaf(ry, a1.w, fmaf(rz, a2.w, bb.w)));
            float4 h;
            h.x = fmaxf(z.x, 0.1f * z.x);
            h.y = fmaxf(z.y, 0.1f * z.y);
            h.z = fmaxf(z.z, 0.1f * z.z);
            h.w = fmaxf(z.w, 0.1f * z.w);
            *(float4*)&hs[warp][lane][g4 * 4] = h;
        }
        __syncwarp();

        // ---- phase 2: out_f = sum_k (h_k . W2[:,f] + b2_f) * x[j_k, f] ----
        unsigned long long acc = 0ull;            // packed (out_f0, out_f1)
        float2 xv_next =
            *(const float2*)(xb + (size_t)idxs[warp][0] * Dc + f0);

#pragma unroll 4
        for (int k = 0; k < Kc; ++k) {
            const float2 xv = xv_next;
            if (k + 1 < Kc)
                xv_next = *(const float2*)(xb + (size_t)idxs[warp][k + 1] * Dc + f0);

            unsigned long long wa0 = b2i0, wb0 = 0ull;
            unsigned long long wa1 = b2i1, wb1 = 0ull;
#pragma unroll
            for (int g4 = 0; g4 < 16; ++g4) {
                // hv.x = (h[4g4], h[4g4+1]), hv.y = (h[4g4+2], h[4g4+3])
                const ulonglong2 hv =
                    *(const ulonglong2*)&hs[warp][k][g4 * 4];
                wa0 = ffma2(hv.x, w2q0[2 * g4],     wa0);
                wb0 = ffma2(hv.y, w2q0[2 * g4 + 1], wb0);
                wa1 = ffma2(hv.x, w2q1[2 * g4],     wa1);
                wb1 = ffma2(hv.y, w2q1[2 * g4 + 1], wb1);
            }
            F2U s0, s1;
            s0.u = fadd2(wa0, wb0);
            s1.u = fadd2(wa1, wb1);
            const float wf0 = s0.f.x + s0.f.y;    // includes b2[f0]
            const float wf1 = s1.f.x + s1.f.y;    // includes b2[f0+1]
            F2U xu; xu.f = xv;
            acc = ffma2(pack2(wf0, wf1), xu.u, acc);
        }
        __syncwarp();

        F2U res; res.u = acc;
        *(float2*)(out + (size_t)p * Dc + f0) = res.f;
    }
}

extern "C" void kernel_launch(void* const* d_in, const int* in_sizes, int n_in,
                              void* d_out, int out_size) {
    const float* x    = (const float*)d_in[0];
    const float* pos  = (const float*)d_in[1];
    const int*   nidx = (const int*)  d_in[2];
    const float* W1   = (const float*)d_in[3];
    const float* b1   = (const float*)d_in[4];
    const float* W2   = (const float*)d_in[5];
    const float* b2   = (const float*)d_in[6];
    float* out = (float*)d_out;
    (void)in_sizes; (void)n_in; (void)out_size;

    pointconv_kernel<<<NBLOCKS, NTHREADS>>>(x, pos, nidx, W1, b1, W2, b2, out);
}

// round 3
// speedup vs baseline: 2.3606x; 2.3606x over previous
#include <cuda_runtime.h>
#include <cuda_bf16.h>
#include <cstdint>
#include <cstddef>

namespace {

constexpr int Nc = 16384, Kc = 32, Dc = 64;
constexpr int POINTS = 4 * Nc;           // 65536
constexpr int NTHR   = 128;              // 4 warps / CTA
constexpr int NCTA   = 444;              // ~3 CTAs / SM

// ---- shared memory layout (byte offsets) ----
constexpr int SM_BFRAG = 0;              // B'' fragment table: 12*8*32*8 = 24576 B
constexpr int SM_W1    = 24576;          // 3*64 f32 = 768 B
constexpr int SM_B1    = 25344;          // 64 f32 = 256 B
constexpr int SM_WARP  = 25600;          // 4 per-warp regions
constexpr int PW       = 9472;           // per-warp: H [32x256B] / Gs [32x288B] overlay
constexpr int SMEM_BYTES = SM_WARP + 4 * PW;   // 63488

__device__ __forceinline__ uint32_t smem_u32(const void* p) {
    uint32_t a;
    asm("{ .reg .u64 t; cvta.to.shared.u64 t, %1; cvt.u32.u64 %0, t; }" : "=r"(a) : "l"(p));
    return a;
}
__device__ __forceinline__ uint32_t prmt_hi(uint32_t u0, uint32_t u1) {
    uint32_t d;  // low16 = top16(u0), high16 = top16(u1)
    asm("prmt.b32 %0, %1, %2, 0x7632;" : "=r"(d) : "r"(u0), "r"(u1));
    return d;
}
__device__ __forceinline__ uint32_t cvt_bf16x2(float hi_val, float lo_val) {
    uint32_t d;  // packs {upper = hi_val, lower = lo_val}
    asm("cvt.rn.bf16x2.f32 %0, %1, %2;" : "=r"(d) : "f"(hi_val), "f"(lo_val));
    return d;
}
__device__ __forceinline__ void mma_bf16(float* c, const uint32_t* a,
                                         uint32_t b0, uint32_t b1) {
    asm volatile(
        "mma.sync.aligned.m16n8k16.row.col.f32.bf16.bf16.f32 "
        "{%0,%1,%2,%3}, {%4,%5,%6,%7}, {%8,%9}, {%0,%1,%2,%3};"
        : "+f"(c[0]), "+f"(c[1]), "+f"(c[2]), "+f"(c[3])
        : "r"(a[0]), "r"(a[1]), "r"(a[2]), "r"(a[3]), "r"(b0), "r"(b1));
}

} // namespace

__global__ void __launch_bounds__(NTHR, 3) pc_mma_kernel(
    const float* __restrict__ x,      // [B, N, 64]
    const float* __restrict__ pos,    // [B, N, 3]
    const int*   __restrict__ nidx,   // [B, N, 32]
    const float* __restrict__ W1,     // [3, 64]
    const float* __restrict__ b1,     // [64]
    const float* __restrict__ W2,     // [64, 64]  (g-major: W2[g*64+f])
    const float* __restrict__ b2,     // [64]
    float*       __restrict__ out)    // [B, N, 64]
{
    extern __shared__ char smem[];
    const uint32_t sb = smem_u32(smem);

    const int tid  = threadIdx.x;
    const int warp = tid >> 5;
    const int lane = tid & 31;
    const int f0   = 2 * lane;

    // ================= one-time init =================
    float* w1s = (float*)(smem + SM_W1);
    float* b1s = (float*)(smem + SM_B1);
    for (int i = tid; i < 3 * Dc; i += NTHR) w1s[i] = W1[i];
    for (int i = tid; i < Dc; i += NTHR)     b1s[i] = b1[i];

    // B'' fragment table: K-ext segments [Bhi | Bhi | Blo], frag order per
    // (ks, ni, lane): b0 = {B[k0][n], B[k0+1][n]}, b1 = {B[k0+8][n], B[k0+9][n]}
    for (int i = tid; i < 12 * 8 * 32; i += NTHR) {
        const int ks = i >> 8, ni = (i >> 5) & 7, ln = i & 31;
        const int n  = ni * 8 + (ln >> 2);
        const int k0 = (ks & 3) * 16 + (ln & 3) * 2;
        const bool lo = (ks >= 8);
        uint2 bf;
        {
            const float v0 = W2[k0 * Dc + n],       v1 = W2[(k0 + 1) * Dc + n];
            const float v2 = W2[(k0 + 8) * Dc + n], v3 = W2[(k0 + 9) * Dc + n];
            const uint32_t u0 = __float_as_uint(v0), u1 = __float_as_uint(v1);
            const uint32_t u2 = __float_as_uint(v2), u3 = __float_as_uint(v3);
            if (!lo) {
                bf.x = (u0 >> 16) | (u1 & 0xFFFF0000u);
                bf.y = (u2 >> 16) | (u3 & 0xFFFF0000u);
            } else {
                const float l0 = v0 - __uint_as_float(u0 & 0xFFFF0000u);
                const float l1 = v1 - __uint_as_float(u1 & 0xFFFF0000u);
                const float l2 = v2 - __uint_as_float(u2 & 0xFFFF0000u);
                const float l3 = v3 - __uint_as_float(u3 & 0xFFFF0000u);
                bf.x = cvt_bf16x2(l1, l0);
                bf.y = cvt_bf16x2(l3, l2);
            }
        }
        *(uint2*)(smem + SM_BFRAG + (size_t)i * 8) = bf;
    }
    __syncthreads();

    // ================= per-lane constants =================
    const float b20 = b2[f0], b21 = b2[f0 + 1];
    char* const wb = smem + SM_WARP + warp * PW;
    const uint32_t wbase = sb + SM_WARP + warp * PW;

    const int rl  = lane & 7;            // swizzle key (= target row & 7)
    const int grp = lane >> 3;
    const int a_row = rl + (grp & 1) * 8;
    const int csel  = grp >> 1;
    const uint32_t a_addr0 = wbase + (uint32_t)a_row * 256u;
    const uint32_t a_addr1 = wbase + (uint32_t)(a_row + 16) * 256u;
    const uint32_t bfrag_base = sb + SM_BFRAG + (uint32_t)lane * 8u;
    const int g = lane >> 2, t = lane & 3;

    // ================= per-point loop (one warp = one point) =================
    for (int p = blockIdx.x * 4 + warp; p < POINTS; p += NCTA * 4) {
        const int b = p >> 14;
        const int j = nidx[(size_t)p * Kc + lane];

        const float cx = pos[(size_t)p * 3 + 0];
        const float cy = pos[(size_t)p * 3 + 1];
        const float cz = pos[(size_t)p * 3 + 2];
        const float* npp = pos + (size_t)(b * Nc + j) * 3;
        const float rx = cx - npp[0], ry = cy - npp[1], rz = cz - npp[2];

        // ---- H build: lane = row k; hi chunks 0-7, lo chunks 8-15, swizzled ----
        {
            const uint32_t hrow = wbase + (uint32_t)lane * 256u;
#pragma unroll
            for (int c8 = 0; c8 < 8; ++c8) {
                uint32_t hq[4], lq[4];
#pragma unroll
                for (int h = 0; h < 2; ++h) {
                    const int g0 = c8 * 8 + h * 4;
                    const float4 a0 = *(const float4*)(w1s + g0);
                    const float4 a1 = *(const float4*)(w1s + Dc + g0);
                    const float4 a2 = *(const float4*)(w1s + 2 * Dc + g0);
                    const float4 bb = *(const float4*)(b1s + g0);
                    float z0 = fmaf(rx, a0.x, fmaf(ry, a1.x, fmaf(rz, a2.x, bb.x)));
                    float z1 = fmaf(rx, a0.y, fmaf(ry, a1.y, fmaf(rz, a2.y, bb.y)));
                    float z2 = fmaf(rx, a0.z, fmaf(ry, a1.z, fmaf(rz, a2.z, bb.z)));
                    float z3 = fmaf(rx, a0.w, fmaf(ry, a1.w, fmaf(rz, a2.w, bb.w)));
                    z0 = fmaxf(z0, 0.1f * z0);
                    z1 = fmaxf(z1, 0.1f * z1);
                    z2 = fmaxf(z2, 0.1f * z2);
                    z3 = fmaxf(z3, 0.1f * z3);
                    const uint32_t u0 = __float_as_uint(z0), u1 = __float_as_uint(z1);
                    const uint32_t u2 = __float_as_uint(z2), u3 = __float_as_uint(z3);
                    hq[2 * h]     = prmt_hi(u0, u1);
                    hq[2 * h + 1] = prmt_hi(u2, u3);
                    const float l0 = z0 - __uint_as_float(u0 & 0xFFFF0000u);
                    const float l1 = z1 - __uint_as_float(u1 & 0xFFFF0000u);
                    const float l2 = z2 - __uint_as_float(u2 & 0xFFFF0000u);
                    const float l3 = z3 - __uint_as_float(u3 & 0xFFFF0000u);
                    lq[2 * h]     = cvt_bf16x2(l1, l0);
                    lq[2 * h + 1] = cvt_bf16x2(l3, l2);
                }
                const uint32_t pc = (uint32_t)(c8 ^ rl);
                asm volatile("st.shared.v4.b32 [%0], {%1,%2,%3,%4};" ::
                             "r"(hrow + (pc << 4)),
                             "r"(hq[0]), "r"(hq[1]), "r"(hq[2]), "r"(hq[3]));
                asm volatile("st.shared.v4.b32 [%0], {%1,%2,%3,%4};" ::
                             "r"(hrow + ((8u + pc) << 4)),
                             "r"(lq[0]), "r"(lq[1]), "r"(lq[2]), "r"(lq[3]));
            }
        }
        __syncwarp();

        // ---- GEMM: G[32x64] = A''[32x192] * B''[192x64], 12 k16-steps ----
        float acc[64];
#pragma unroll
        for (int i = 0; i < 64; ++i) acc[i] = 0.0f;

#pragma unroll
        for (int ks = 0; ks < 12; ++ks) {
            const uint32_t cl = ((ks >= 4 && ks < 8) ? 8u : 0u)
                              + (uint32_t)(ks & 3) * 2u + (uint32_t)csel;
            const uint32_t coff = ((cl ^ (uint32_t)rl) << 4);
            uint32_t a0[4], a1[4];
            asm volatile("ldmatrix.sync.aligned.m8n8.x4.shared.b16 {%0,%1,%2,%3}, [%4];"
                         : "=r"(a0[0]), "=r"(a0[1]), "=r"(a0[2]), "=r"(a0[3])
                         : "r"(a_addr0 + coff));
            asm volatile("ldmatrix.sync.aligned.m8n8.x4.shared.b16 {%0,%1,%2,%3}, [%4];"
                         : "=r"(a1[0]), "=r"(a1[1]), "=r"(a1[2]), "=r"(a1[3])
                         : "r"(a_addr1 + coff));
            const uint32_t bptr = bfrag_base + (uint32_t)ks * 2048u;
#pragma unroll
            for (int ni = 0; ni < 8; ++ni) {
                uint32_t bv0, bv1;
                asm volatile("ld.shared.v2.u32 {%0,%1}, [%2];"
                             : "=r"(bv0), "=r"(bv1) : "r"(bptr + ni * 256u));
                mma_bf16(&acc[ni * 8],     a0, bv0, bv1);
                mma_bf16(&acc[ni * 8 + 4], a1, bv0, bv1);
            }
        }

        // ---- transpose G to row-major Gs (stride 288 B), same warp region ----
#pragma unroll
        for (int ni = 0; ni < 8; ++ni) {
#pragma unroll
            for (int mi = 0; mi < 2; ++mi) {
                const float* c = &acc[ni * 8 + mi * 4];
                char* r0 = wb + (mi * 16 + g) * 288 + ni * 32 + t * 8;
                *(float2*)r0         = make_float2(c[0], c[1]);
                *(float2*)(r0 + 8 * 288) = make_float2(c[2], c[3]);
            }
        }
        __syncwarp();

        // ---- epilogue: out[f] = sum_k (G[k,f] + b2[f]) * x[j_k, f] ----
        const float* xb = x + (size_t)b * Nc * Dc;
        float o0 = 0.0f, o1 = 0.0f;
#pragma unroll
        for (int kb = 0; kb < 4; ++kb) {
            float2 xv[8];
#pragma unroll
            for (int u = 0; u < 8; ++u) {
                const int jk = __shfl_sync(0xFFFFFFFFu, j, kb * 8 + u);
                xv[u] = *(const float2*)(xb + (size_t)jk * Dc + f0);
            }
#pragma unroll
            for (int u = 0; u < 8; ++u) {
                const float2 g2 = *(const float2*)(wb + (kb * 8 + u) * 288 + lane * 8);
                o0 = fmaf(g2.x + b20, xv[u].x, o0);
                o1 = fmaf(g2.y + b21, xv[u].y, o1);
            }
        }
        __syncwarp();   // Gs region reused as H next iteration

        *(float2*)(out + (size_t)p * Dc + f0) = make_float2(o0, o1);
    }
}

extern "C" void kernel_launch(void* const* d_in, const int* in_sizes, int n_in,
                              void* d_out, int out_size) {
    const float* x    = (const float*)d_in[0];
    const float* pos  = (const float*)d_in[1];
    const int*   nidx = (const int*)  d_in[2];
    const float* W1   = (const float*)d_in[3];
    const float* b1   = (const float*)d_in[4];
    const float* W2   = (const float*)d_in[5];
    const float* b2   = (const float*)d_in[6];
    float* out = (float*)d_out;
    (void)in_sizes; (void)n_in; (void)out_size;

    cudaFuncSetAttribute(pc_mma_kernel, cudaFuncAttributeMaxDynamicSharedMemorySize,
                         SMEM_BYTES);
    pc_mma_kernel<<<NCTA, NTHR, SMEM_BYTES>>>(x, pos, nidx, W1, b1, W2, b2, out);
}